// round 1
// baseline (speedup 1.0000x reference)
#include <cuda_runtime.h>
#include <cstdint>

#define NN 1000000
#define NE 16000000

// ---- scratch (device globals; no allocations allowed) ----
__device__ int    g_deg[NN];
__device__ float  g_dis[NN];
__device__ float  g_u[NN];
__device__ float  g_acc1[NN];
__device__ float2 g_t[NN];
__device__ float2 g_acc2[NN];

// ---------------------------------------------------------------------------
__global__ __launch_bounds__(256) void k_zero() {
    int i = blockIdx.x * blockDim.x + threadIdx.x;
    if (i < NN) {
        g_deg[i]  = 1;                 // self-loop contributes 1 to degree
        g_acc1[i] = 0.0f;
        g_acc2[i] = make_float2(0.0f, 0.0f);
    }
}

// degree count over target (col) indices; 4 edges per thread
__global__ __launch_bounds__(256) void k_deg(const int* __restrict__ col, int E) {
    int i = (blockIdx.x * blockDim.x + threadIdx.x) * 4;
    if (i + 3 < E) {
        int4 c = *reinterpret_cast<const int4*>(col + i);
        atomicAdd(&g_deg[c.x], 1);
        atomicAdd(&g_deg[c.y], 1);
        atomicAdd(&g_deg[c.z], 1);
        atomicAdd(&g_deg[c.w], 1);
    }
}

// dis = rsqrt(deg); u = dis * x
__global__ __launch_bounds__(256) void k_prep(const float* __restrict__ x) {
    int i = blockIdx.x * blockDim.x + threadIdx.x;
    if (i < NN) {
        float d = rsqrtf((float)g_deg[i]);
        g_dis[i] = d;
        g_u[i]   = d * x[i];
    }
}

// scatter layer-1 messages: acc1[col] += u[row]
__global__ __launch_bounds__(256) void k_scat1(const int* __restrict__ row,
                                               const int* __restrict__ col, int E) {
    int i = (blockIdx.x * blockDim.x + threadIdx.x) * 4;
    if (i + 3 < E) {
        int4 r = *reinterpret_cast<const int4*>(row + i);
        int4 c = *reinterpret_cast<const int4*>(col + i);
        atomicAdd(&g_acc1[c.x], __ldg(&g_u[r.x]));
        atomicAdd(&g_acc1[c.y], __ldg(&g_u[r.y]));
        atomicAdd(&g_acc1[c.z], __ldg(&g_u[r.z]));
        atomicAdd(&g_acc1[c.w], __ldg(&g_u[r.w]));
    }
}

// per-node MLP: s -> relu(W1*s+b1) -> @W2 ; t = dis * g
__global__ __launch_bounds__(256) void k_node2(const float4* __restrict__ W1,
                                               const float4* __restrict__ b1,
                                               const float4* __restrict__ W2) {
    int i = blockIdx.x * blockDim.x + threadIdx.x;
    if (i >= NN) return;
    float d = g_dis[i];
    float s = d * (g_acc1[i] + g_u[i]);
    float g0 = 0.0f, g1 = 0.0f;
#pragma unroll
    for (int q = 0; q < 4; q++) {
        float4 w1 = __ldg(&W1[q]);
        float4 bb = __ldg(&b1[q]);
        float4 e0 = __ldg(&W2[2 * q]);       // (k0c0,k0c1,k1c0,k1c1)
        float4 e1 = __ldg(&W2[2 * q + 1]);   // (k2c0,k2c1,k3c0,k3c1)
        float h0 = fmaxf(fmaf(s, w1.x, bb.x), 0.0f);
        float h1 = fmaxf(fmaf(s, w1.y, bb.y), 0.0f);
        float h2 = fmaxf(fmaf(s, w1.z, bb.z), 0.0f);
        float h3 = fmaxf(fmaf(s, w1.w, bb.w), 0.0f);
        g0 = fmaf(h0, e0.x, g0); g1 = fmaf(h0, e0.y, g1);
        g0 = fmaf(h1, e0.z, g0); g1 = fmaf(h1, e0.w, g1);
        g0 = fmaf(h2, e1.x, g0); g1 = fmaf(h2, e1.y, g1);
        g0 = fmaf(h3, e1.z, g0); g1 = fmaf(h3, e1.w, g1);
    }
    g_t[i] = make_float2(d * g0, d * g1);
}

__device__ __forceinline__ void red_add_v2(float2* addr, float2 v) {
    asm volatile("red.global.add.v2.f32 [%0], {%1, %2};"
                 :: "l"(addr), "f"(v.x), "f"(v.y) : "memory");
}

// scatter layer-2 messages: acc2[col] += t[row] (vectorized f32x2 reduction)
__global__ __launch_bounds__(256) void k_scat2(const int* __restrict__ row,
                                               const int* __restrict__ col, int E) {
    int i = (blockIdx.x * blockDim.x + threadIdx.x) * 4;
    if (i + 3 < E) {
        int4 r = *reinterpret_cast<const int4*>(row + i);
        int4 c = *reinterpret_cast<const int4*>(col + i);
        float2 t0 = g_t[r.x];
        float2 t1 = g_t[r.y];
        float2 t2 = g_t[r.z];
        float2 t3 = g_t[r.w];
        red_add_v2(&g_acc2[c.x], t0);
        red_add_v2(&g_acc2[c.y], t1);
        red_add_v2(&g_acc2[c.z], t2);
        red_add_v2(&g_acc2[c.w], t3);
    }
}

// final: out = dis*(acc2 + t) + b2, then log_softmax over 2 classes
__global__ __launch_bounds__(256) void k_out(const float* __restrict__ b2,
                                             float2* __restrict__ out) {
    int i = blockIdx.x * blockDim.x + threadIdx.x;
    if (i >= NN) return;
    float d  = g_dis[i];
    float2 a = g_acc2[i];
    float2 t = g_t[i];
    float b20 = __ldg(&b2[0]);
    float b21 = __ldg(&b2[1]);
    float o0 = fmaf(d, a.x + t.x, b20);
    float o1 = fmaf(d, a.y + t.y, b21);
    float m  = fmaxf(o0, o1);
    float lse = m + log1pf(__expf(fminf(o0, o1) - m));
    out[i] = make_float2(o0 - lse, o1 - lse);
}

// ---------------------------------------------------------------------------
extern "C" void kernel_launch(void* const* d_in, const int* in_sizes, int n_in,
                              void* d_out, int out_size) {
    const float* x   = (const float*)d_in[0];
    const int*   ei  = (const int*)d_in[1];
    const float* W1  = (const float*)d_in[2];
    const float* b1  = (const float*)d_in[3];
    const float* W2  = (const float*)d_in[4];
    const float* b2  = (const float*)d_in[5];
    float2* out = (float2*)d_out;

    const int E = in_sizes[1] / 2;      // edge_index is [2, E]
    const int* row = ei;                // source
    const int* col = ei + E;            // target

    const int TB = 256;
    const int nodeBlocks = (NN + TB - 1) / TB;
    const int edgeBlocks = (E / 4 + TB - 1) / TB;

    k_zero <<<nodeBlocks, TB>>>();
    k_deg  <<<edgeBlocks, TB>>>(col, E);
    k_prep <<<nodeBlocks, TB>>>(x);
    k_scat1<<<edgeBlocks, TB>>>(row, col, E);
    k_node2<<<nodeBlocks, TB>>>((const float4*)W1, (const float4*)b1,
                                (const float4*)W2);
    k_scat2<<<edgeBlocks, TB>>>(row, col, E);
    k_out  <<<nodeBlocks, TB>>>(b2, out);
}